// round 4
// baseline (speedup 1.0000x reference)
#include <cuda_runtime.h>
#include <cfloat>

// Symmetric squared-Hausdorff per batch, exact early-break pruning with a
// PER-BLOCK lower bound (fused — no separate LB kernel).
//
// d^2(p,g) = |p|^2 + s,  s = |g|^2 - 2 p.g  (|p|^2 added after the min).
// Inner points packed in smem as f32x2 pairs; scan = 3 FFMA2 + 2 FMNMX / 2 evals.
// Each block: stage inner -> blockLB = exact min-d^2 of block's max-radius
// outer point -> per-point scan breaks once partial min < LB - margin.
// Broken points record partials < LB <= answer (can't win the max); the
// argmax point never breaks -> exact result.

#define BATCH   16
#define NPTS    4096
#define NPAIRS  (NPTS / 2)          // 2048 packed pairs (slots)
#define T2      512
#define PTSBLK  256                 // outer points per block (2 lanes/pt)
#define OCH     (NPTS / PTSBLK)     // 16
#define HPAIRS  (NPAIRS / 2)        // 1024 slot-steps per lane half

__device__ float g_bmax[2][BATCH][OCH];

typedef unsigned long long u64t;

__device__ __forceinline__ u64t fma2(u64t a, u64t b, u64t c) {
    u64t d;
    asm("fma.rn.f32x2 %0, %1, %2, %3;" : "=l"(d) : "l"(a), "l"(b), "l"(c));
    return d;
}
__device__ __forceinline__ u64t pk(float lo, float hi) {
    u64t d;
    asm("mov.b64 %0, {%1, %2};" : "=l"(d) : "f"(lo), "f"(hi));
    return d;
}
__device__ __forceinline__ float2 upk(u64t v) {
    float2 r;
    asm("mov.b64 {%0, %1}, %2;" : "=f"(r.x), "=f"(r.y) : "l"(v));
    return r;
}

__global__ void __launch_bounds__(T2)
hd_main(const float* __restrict__ preds, const float* __restrict__ gts) {
    extern __shared__ __align__(16) ulonglong2 shv[];   // 2048 slots * 32B = 64KB
    float* shf = (float*)shv;

    const int och = blockIdx.x, b = blockIdx.y, dir = blockIdx.z;
    const float* __restrict__ outer = (dir == 0 ? preds : gts) + (size_t)b * NPTS * 3;
    const float* __restrict__ inner = (dir == 0 ? gts : preds) + (size_t)b * NPTS * 3;
    const int tid = threadIdx.x;

    // ---- stage inner pairs; halves INTERLEAVED: pair pj -> slot ----
    //   pj < HPAIRS  -> slot 2*pj     (read by lane half 0)
    //   pj >= HPAIRS -> slot 2*(pj-HPAIRS)+1  (read by lane half 1)
    // slot layout (8 floats): {-2x0,-2x1,-2y0,-2y1,-2z0,-2z1,w0,w1}
#pragma unroll
    for (int k = 0; k < NPAIRS / T2; k++) {
        int pj = tid + k * T2;
        const float* gp = inner + (size_t)pj * 6;
        float x0 = gp[0], y0 = gp[1], z0 = gp[2];
        float x1 = gp[3], y1 = gp[4], z1 = gp[5];
        int s = (pj < HPAIRS) ? (pj * 2) : ((pj - HPAIRS) * 2 + 1);
        float4 v0 = make_float4(-2.0f*x0, -2.0f*x1, -2.0f*y0, -2.0f*y1);
        float4 v1 = make_float4(-2.0f*z0, -2.0f*z1,
                                fmaf(x0, x0, fmaf(y0, y0, z0*z0)),
                                fmaf(x1, x1, fmaf(y1, y1, z1*z1)));
        ((float4*)shf)[s * 2 + 0] = v0;
        ((float4*)shf)[s * 2 + 1] = v1;
    }

    // ---- block candidate: max-radius outer point among this block's 256 ----
    __shared__ float s_wr[T2 / 32];
    __shared__ int   s_wi[T2 / 32];
    __shared__ float s_cand[4];                          // cx, cy, cz, crq
    __shared__ float s_wmin[T2 / 32];
    __shared__ float s_lb;
    {
        float r = -1.0f; int idx = 0;
        if (tid < PTSBLK) {
            int i = och * PTSBLK + tid;
            float x = outer[3*i], y = outer[3*i+1], z = outer[3*i+2];
            r = fmaf(x, x, fmaf(y, y, z * z));
            idx = i;
        }
#pragma unroll
        for (int off = 16; off; off >>= 1) {
            float r2 = __shfl_xor_sync(0xffffffffu, r, off);
            int   i2 = __shfl_xor_sync(0xffffffffu, idx, off);
            if (r2 > r || (r2 == r && i2 < idx)) { r = r2; idx = i2; }
        }
        if ((tid & 31) == 0) { s_wr[tid >> 5] = r; s_wi[tid >> 5] = idx; }
    }
    __syncthreads();    // staging visible + warp argmax partials visible
    if (tid == 0) {
        float r = s_wr[0]; int idx = s_wi[0];
#pragma unroll
        for (int w = 1; w < T2 / 32; w++)
            if (s_wr[w] > r || (s_wr[w] == r && s_wi[w] < idx)) { r = s_wr[w]; idx = s_wi[w]; }
        float cx = outer[3*idx], cy = outer[3*idx+1], cz = outer[3*idx+2];
        s_cand[0] = cx; s_cand[1] = cy; s_cand[2] = cz;
        s_cand[3] = fmaf(cx, cx, fmaf(cy, cy, cz * cz));
    }
    __syncthreads();

    // ---- cooperative exact min-d^2 of candidate over all 4096 inner pts ----
    {
        const float cx = s_cand[0], cy = s_cand[1], cz = s_cand[2];
        float mn = FLT_MAX;
#pragma unroll
        for (int k = 0; k < NPAIRS / T2; k++) {
            int slot = tid + k * T2;
            const float* e = shf + slot * 8;
            float t0 = fmaf(e[0], cx, e[6]);
            t0 = fmaf(e[2], cy, t0);
            t0 = fmaf(e[4], cz, t0);
            float t1 = fmaf(e[1], cx, e[7]);
            t1 = fmaf(e[3], cy, t1);
            t1 = fmaf(e[5], cz, t1);
            mn = fminf(mn, fminf(t0, t1));
        }
#pragma unroll
        for (int off = 16; off; off >>= 1)
            mn = fminf(mn, __shfl_xor_sync(0xffffffffu, mn, off));
        if ((tid & 31) == 0) s_wmin[tid >> 5] = mn;
    }
    __syncthreads();
    if (tid == 0) {
        float m = s_wmin[0];
#pragma unroll
        for (int w = 1; w < T2 / 32; w++) m = fminf(m, s_wmin[w]);
        float lb = m + s_cand[3];                       // exact min-d^2 of candidate
        s_lb = lb - fabsf(lb) * 1e-5f - 1e-12f;         // safety margin
    }
    __syncthreads();

    // ---- early-break scan: 2 lanes per outer point, interleaved halves ----
    const int p_idx = och * PTSBLK + (tid >> 1);
    const int half  = tid & 1;
    const float x = outer[3*p_idx], y = outer[3*p_idx+1], z = outer[3*p_idx+2];
    const float rq = fmaf(x, x, fmaf(y, y, z * z));
    const u64t px2 = pk(x, x), py2 = pk(y, y), pz2 = pk(z, z);
    const float lbs = s_lb - rq;                        // threshold, shifted domain

    float mnA = FLT_MAX, mnB = FLT_MAX;
    for (int jp = 0; jp < HPAIRS; jp += 4) {
#pragma unroll
        for (int c = 0; c < 2; c++) {
            int slot = (jp + c) * 2 + half;
            ulonglong2 ab = shv[slot * 2 + 0];          // {gx2, gy2}
            ulonglong2 cd = shv[slot * 2 + 1];          // {gz2, gw2}
            u64t t = fma2(ab.x, px2, cd.y);
            t = fma2(ab.y, py2, t);
            t = fma2(cd.x, pz2, t);
            float2 tv = upk(t);
            mnA = fminf(mnA, fminf(tv.x, tv.y));
        }
#pragma unroll
        for (int c = 2; c < 4; c++) {
            int slot = (jp + c) * 2 + half;
            ulonglong2 ab = shv[slot * 2 + 0];
            ulonglong2 cd = shv[slot * 2 + 1];
            u64t t = fma2(ab.x, px2, cd.y);
            t = fma2(ab.y, py2, t);
            t = fma2(cd.x, pz2, t);
            float2 tv = upk(t);
            mnB = fminf(mnB, fminf(tv.x, tv.y));
        }
        if (fminf(mnA, mnB) < lbs) break;               // certified non-argmax
    }

    float mn = fminf(mnA, mnB);
    mn = fminf(mn, __shfl_xor_sync(0xffffffffu, mn, 1)); // join the two halves
    float v = mn + rq;

    // ---- block max reduce ----
#pragma unroll
    for (int off = 16; off; off >>= 1)
        v = fmaxf(v, __shfl_xor_sync(0xffffffffu, v, off));
    __shared__ float wm[T2 / 32];
    if ((tid & 31) == 0) wm[tid >> 5] = v;
    __syncthreads();
    if (tid == 0) {
        float m = wm[0];
#pragma unroll
        for (int w = 1; w < T2 / 32; w++) m = fmaxf(m, wm[w]);
        g_bmax[dir][b][och] = m;
    }
}

__global__ void hd_combine(float* __restrict__ out) {
    const int b = blockIdx.x, tid = threadIdx.x;        // 32 threads
    float v0 = (tid < OCH) ? g_bmax[0][b][tid] : -FLT_MAX;
    float v1 = (tid < OCH) ? g_bmax[1][b][tid] : -FLT_MAX;
#pragma unroll
    for (int off = 16; off; off >>= 1) {
        v0 = fmaxf(v0, __shfl_xor_sync(0xffffffffu, v0, off));
        v1 = fmaxf(v1, __shfl_xor_sync(0xffffffffu, v1, off));
    }
    if (tid == 0) out[b] = 0.5f * (v0 + v1);
}

extern "C" void kernel_launch(void* const* d_in, const int* in_sizes, int n_in,
                              void* d_out, int out_size) {
    const float* preds = (const float*)d_in[0];
    const float* gts   = (const float*)d_in[1];
    float* out = (float*)d_out;

    const int smem = NPAIRS * 2 * sizeof(ulonglong2);   // 64 KB
    cudaFuncSetAttribute(hd_main,
                         cudaFuncAttributeMaxDynamicSharedMemorySize, smem);

    hd_main<<<dim3(OCH, BATCH, 2), T2, smem>>>(preds, gts);
    hd_combine<<<BATCH, 32>>>(out);
}

// round 5
// speedup vs baseline: 1.2237x; 1.2237x over previous
#include <cuda_runtime.h>
#include <cfloat>

// Symmetric squared-Hausdorff per batch.
// d^2(p,g) = |p|^2 + s, s = |g|^2 - 2 p.g; |p|^2 added after the min.
// f32x2-packed inner pairs in smem: 3 FFMA2 + 2 FMNMX per 2 evals.
// OPT=8 outer points per lane -> each 32B smem slot feeds 16 evals (LDS no
// longer the binder; fma pipe is). Early break only at 16-iter chunk
// granularity via a warp-uniform vote against a precomputed global LB.

#define BATCH   16
#define NPTS    4096
#define THREADS 256
#define OPT     8                        // outer points per thread
#define PTSBLK  (THREADS * OPT)          // 2048
#define OCH     (NPTS / PTSBLK)          // 2
#define ICH     8                        // inner chunks
#define ICN     (NPTS / ICH)             // 512 inner points / chunk
#define IPAIRS  (ICN / 2)                // 256 pairs / chunk (8KB smem)
#define CHUNK   16                       // pair-iters per break check
#define NCHUNK  (IPAIRS / CHUNK)         // 16

__device__ float g_lb[2][BATCH];                    // LB with margin applied
__device__ float g_partial[2][BATCH][ICH][NPTS];    // per-point partial mins

typedef unsigned long long u64t;

__device__ __forceinline__ u64t fma2(u64t a, u64t b, u64t c) {
    u64t d;
    asm("fma.rn.f32x2 %0, %1, %2, %3;" : "=l"(d) : "l"(a), "l"(b), "l"(c));
    return d;
}
__device__ __forceinline__ u64t pk(float lo, float hi) {
    u64t d;
    asm("mov.b64 %0, {%1, %2};" : "=l"(d) : "f"(lo), "f"(hi));
    return d;
}
__device__ __forceinline__ float2 upk(u64t v) {
    float2 r;
    asm("mov.b64 {%0, %1}, %2;" : "=f"(r.x), "=f"(r.y) : "l"(v));
    return r;
}

// ---------------- K1: global LB from max-radius outer point ----------------
__global__ void __launch_bounds__(THREADS)
hd_lb(const float* __restrict__ preds, const float* __restrict__ gts) {
    const int b = blockIdx.x, dir = blockIdx.y;
    const float* __restrict__ outer = (dir == 0 ? preds : gts) + (size_t)b * NPTS * 3;
    const float* __restrict__ inner = (dir == 0 ? gts : preds) + (size_t)b * NPTS * 3;
    const int tid = threadIdx.x;

    float bestr = -1.0f; int besti = 0;
    for (int i = tid; i < NPTS; i += THREADS) {
        float x = outer[3*i], y = outer[3*i+1], z = outer[3*i+2];
        float r = fmaf(x, x, fmaf(y, y, z * z));
        if (r > bestr || (r == bestr && i < besti)) { bestr = r; besti = i; }
    }
#pragma unroll
    for (int off = 16; off; off >>= 1) {
        float r2 = __shfl_xor_sync(0xffffffffu, bestr, off);
        int   i2 = __shfl_xor_sync(0xffffffffu, besti, off);
        if (r2 > bestr || (r2 == bestr && i2 < besti)) { bestr = r2; besti = i2; }
    }
    __shared__ float sr[THREADS/32]; __shared__ int si[THREADS/32];
    __shared__ int s_pi;
    if ((tid & 31) == 0) { sr[tid>>5] = bestr; si[tid>>5] = besti; }
    __syncthreads();
    if (tid == 0) {
        float r = sr[0]; int i = si[0];
#pragma unroll
        for (int w = 1; w < THREADS/32; w++)
            if (sr[w] > r || (sr[w] == r && si[w] < i)) { r = sr[w]; i = si[w]; }
        s_pi = i;
    }
    __syncthreads();

    const int pi = s_pi;
    const float px = outer[3*pi], py = outer[3*pi+1], pz = outer[3*pi+2];
    const float rq = fmaf(px, px, fmaf(py, py, pz * pz));

    float mn = FLT_MAX;
    for (int j = tid; j < NPTS; j += THREADS) {
        float gx = inner[3*j], gy = inner[3*j+1], gz = inner[3*j+2];
        float gw = fmaf(gx, gx, fmaf(gy, gy, gz * gz));
        float t = fmaf(-2.0f * gx, px, gw);
        t = fmaf(-2.0f * gy, py, t);
        t = fmaf(-2.0f * gz, pz, t);
        mn = fminf(mn, t);
    }
#pragma unroll
    for (int off = 16; off; off >>= 1)
        mn = fminf(mn, __shfl_xor_sync(0xffffffffu, mn, off));
    __shared__ float sm[THREADS/32];
    if ((tid & 31) == 0) sm[tid>>5] = mn;
    __syncthreads();
    if (tid == 0) {
        float m = sm[0];
#pragma unroll
        for (int w = 1; w < THREADS/32; w++) m = fminf(m, sm[w]);
        float lb = m + rq;                               // exact min-d^2 of candidate
        g_lb[dir][b] = lb - fabsf(lb) * 1e-5f - 1e-12f;  // safety margin
    }
}

// ---------------- K2: main scan (branchless chunks + coarse vote) ----------
__global__ void __launch_bounds__(THREADS)
hd_main(const float* __restrict__ preds, const float* __restrict__ gts) {
    __shared__ __align__(16) ulonglong2 shv[IPAIRS * 2];   // 8KB

    const int ich = blockIdx.x & (ICH - 1);
    const int och = blockIdx.x >> 3;
    const int b   = blockIdx.y;
    const int dir = blockIdx.z;
    const float* __restrict__ outer = (dir == 0 ? preds : gts) + (size_t)b * NPTS * 3;
    const float* __restrict__ inner = (dir == 0 ? gts : preds) + (size_t)b * NPTS * 3;
    const int tid = threadIdx.x;

    // stage 256 pairs (1 per thread), slot layout:
    // {-2x0,-2x1,-2y0,-2y1},{-2z0,-2z1,w0,w1}
    {
        const int pj = tid;
        const float* gp = inner + (size_t)(ich * ICN + 2 * pj) * 3;
        float x0 = gp[0], y0 = gp[1], z0 = gp[2];
        float x1 = gp[3], y1 = gp[4], z1 = gp[5];
        float4 v0 = make_float4(-2.0f*x0, -2.0f*x1, -2.0f*y0, -2.0f*y1);
        float4 v1 = make_float4(-2.0f*z0, -2.0f*z1,
                                fmaf(x0, x0, fmaf(y0, y0, z0*z0)),
                                fmaf(x1, x1, fmaf(y1, y1, z1*z1)));
        ((float4*)shv)[pj * 2 + 0] = v0;
        ((float4*)shv)[pj * 2 + 1] = v1;
    }
    __syncthreads();

    // per-thread outer points
    u64t px2[OPT], py2[OPT], pz2[OPT];
    float rq[OPT], mn[OPT];
    int i0 = och * PTSBLK + tid;
#pragma unroll
    for (int o = 0; o < OPT; o++) {
        int i = i0 + o * THREADS;
        float x = outer[3*i], y = outer[3*i+1], z = outer[3*i+2];
        px2[o] = pk(x, x);
        py2[o] = pk(y, y);
        pz2[o] = pk(z, z);
        rq[o]  = fmaf(x, x, fmaf(y, y, z * z));
        mn[o]  = FLT_MAX;
    }
    const float lbm = g_lb[dir][b];

    // scan: branchless 16-iter chunks, warp-uniform break vote per chunk
    for (int ch = 0; ch < NCHUNK; ch++) {
#pragma unroll 8
        for (int it = 0; it < CHUNK; it++) {
            int slot = ch * CHUNK + it;
            ulonglong2 ab = shv[slot * 2 + 0];   // {gx2, gy2}
            ulonglong2 cd = shv[slot * 2 + 1];   // {gz2, gw2}
#pragma unroll
            for (int o = 0; o < OPT; o++) {
                u64t t = fma2(ab.x, px2[o], cd.y);
                t = fma2(ab.y, py2[o], t);
                t = fma2(cd.x, pz2[o], t);
                float2 tv = upk(t);
                mn[o] = fminf(mn[o], fminf(tv.x, tv.y));
            }
        }
        // all OPT points of all 32 lanes certified non-argmax? -> stop
        float worst = mn[0] + rq[0];
#pragma unroll
        for (int o = 1; o < OPT; o++) worst = fmaxf(worst, mn[o] + rq[o]);
        if (__all_sync(0xffffffffu, worst < lbm)) break;
    }

    // per-point partial (exact for non-broken; < LB for broken -> harmless)
    float* dst = &g_partial[dir][b][ich][0];
#pragma unroll
    for (int o = 0; o < OPT; o++)
        dst[i0 + o * THREADS] = mn[o] + rq[o];
}

// ---------------- K3: combine (min over ICH, max over points) --------------
__global__ void __launch_bounds__(THREADS)
hd_combine(float* __restrict__ out) {
    const int b   = blockIdx.x;
    const int tid = threadIdx.x;

    float m0 = -FLT_MAX, m1 = -FLT_MAX;
#pragma unroll
    for (int it = 0; it < NPTS / (THREADS * 4); it++) {     // 4 iters
        int o = tid * 4 + it * THREADS * 4;
        float4 v0 = *(const float4*)&g_partial[0][b][0][o];
        float4 v1 = *(const float4*)&g_partial[1][b][0][o];
#pragma unroll
        for (int c = 1; c < ICH; c++) {
            float4 a = *(const float4*)&g_partial[0][b][c][o];
            float4 d = *(const float4*)&g_partial[1][b][c][o];
            v0.x = fminf(v0.x, a.x); v0.y = fminf(v0.y, a.y);
            v0.z = fminf(v0.z, a.z); v0.w = fminf(v0.w, a.w);
            v1.x = fminf(v1.x, d.x); v1.y = fminf(v1.y, d.y);
            v1.z = fminf(v1.z, d.z); v1.w = fminf(v1.w, d.w);
        }
        m0 = fmaxf(m0, fmaxf(fmaxf(v0.x, v0.y), fmaxf(v0.z, v0.w)));
        m1 = fmaxf(m1, fmaxf(fmaxf(v1.x, v1.y), fmaxf(v1.z, v1.w)));
    }
#pragma unroll
    for (int off = 16; off; off >>= 1) {
        m0 = fmaxf(m0, __shfl_xor_sync(0xffffffffu, m0, off));
        m1 = fmaxf(m1, __shfl_xor_sync(0xffffffffu, m1, off));
    }
    __shared__ float w0[THREADS / 32], w1[THREADS / 32];
    if ((tid & 31) == 0) { w0[tid >> 5] = m0; w1[tid >> 5] = m1; }
    __syncthreads();
    if (tid == 0) {
        float a = w0[0], c = w1[0];
#pragma unroll
        for (int w = 1; w < THREADS / 32; w++) {
            a = fmaxf(a, w0[w]);
            c = fmaxf(c, w1[w]);
        }
        out[b] = 0.5f * (a + c);
    }
}

extern "C" void kernel_launch(void* const* d_in, const int* in_sizes, int n_in,
                              void* d_out, int out_size) {
    const float* preds = (const float*)d_in[0];
    const float* gts   = (const float*)d_in[1];
    float* out = (float*)d_out;

    hd_lb<<<dim3(BATCH, 2), THREADS>>>(preds, gts);
    hd_main<<<dim3(OCH * ICH, BATCH, 2), THREADS>>>(preds, gts);   // 16x16x2=512
    hd_combine<<<BATCH, THREADS>>>(out);
}

// round 6
// speedup vs baseline: 1.5989x; 1.3066x over previous
#include <cuda_runtime.h>
#include <cfloat>

// Symmetric squared-Hausdorff per batch, two-phase exact pruning.
// d^2(p,g) = |p|^2 + s, s = |g|^2 - 2 p.g  (|p|^2 added after the min).
//
// Per block (one quarter of outer points, ALL inner points in 64KB smem):
//  LB   : exact full min-d^2 of the block's max-radius outer point (valid
//         global lower bound of the answer), shrunk by a safety margin.
//  Ph.1 : branchless scan of the FIRST 512 inner points for all 1024 outer
//         points (f32x2 packed: 3 FFMA2 + 2 FMNMX per 2 evals, OPT=4).
//  Ph.2 : points whose phase-1 partial >= LB are rescanned over the
//         remaining 3584 inner points, ONE POINT PER WARP, with an O(1)
//         __any_sync certification break every 8 iterations.
// Certified points record partials < LB <= answer (cannot win the max);
// the argmax never certifies and is computed exactly. Deterministic.

#define BATCH   16
#define NPTS    4096
#define T       256
#define OPT     4
#define PTSBLK  (T * OPT)            // 1024 outer points per block
#define OCH     (NPTS / PTSBLK)      // 4
#define NSLOTS  (NPTS / 2)           // 2048 packed inner pair-slots
#define P1SLOTS 256                  // phase-1: first 512 inner points
#define P2ITER  ((NSLOTS - P1SLOTS) / 32)   // 56 lane-iters in phase 2

__device__ float g_bmax[2][BATCH][OCH];

typedef unsigned long long u64t;

__device__ __forceinline__ u64t fma2(u64t a, u64t b, u64t c) {
    u64t d;
    asm("fma.rn.f32x2 %0, %1, %2, %3;" : "=l"(d) : "l"(a), "l"(b), "l"(c));
    return d;
}
__device__ __forceinline__ u64t pk(float lo, float hi) {
    u64t d;
    asm("mov.b64 %0, {%1, %2};" : "=l"(d) : "f"(lo), "f"(hi));
    return d;
}
__device__ __forceinline__ float2 upk(u64t v) {
    float2 r;
    asm("mov.b64 {%0, %1}, %2;" : "=f"(r.x), "=f"(r.y) : "l"(v));
    return r;
}

__global__ void __launch_bounds__(T)
hd_main(const float* __restrict__ preds, const float* __restrict__ gts) {
    extern __shared__ __align__(16) ulonglong2 shv[];   // NSLOTS*2 = 64 KB
    float* shf = (float*)shv;
    __shared__ float s_val[PTSBLK];          // per-point d^2 (partial or exact)
    __shared__ unsigned short s_list[PTSBLK];
    __shared__ int   s_cnt;
    __shared__ float s_lb;
    __shared__ float s_red[T / 32];
    __shared__ int   s_redi[T / 32];
    __shared__ float s_cand[4];

    const int och = blockIdx.x, b = blockIdx.y, dir = blockIdx.z;
    const float* __restrict__ outer = (dir == 0 ? preds : gts) + (size_t)b * NPTS * 3;
    const float* __restrict__ inner = (dir == 0 ? gts : preds) + (size_t)b * NPTS * 3;
    const int tid = threadIdx.x;
    if (tid == 0) s_cnt = 0;

    // ---- stage ALL inner pairs: slot = {-2x0,-2x1,-2y0,-2y1},{-2z0,-2z1,w0,w1}
#pragma unroll
    for (int k = 0; k < NSLOTS / T; k++) {          // 8 slots/thread
        int pj = tid + k * T;
        const float* gp = inner + (size_t)pj * 6;
        float x0 = gp[0], y0 = gp[1], z0 = gp[2];
        float x1 = gp[3], y1 = gp[4], z1 = gp[5];
        ((float4*)shf)[pj * 2 + 0] = make_float4(-2.f*x0, -2.f*x1, -2.f*y0, -2.f*y1);
        ((float4*)shf)[pj * 2 + 1] = make_float4(-2.f*z0, -2.f*z1,
                                fmaf(x0, x0, fmaf(y0, y0, z0*z0)),
                                fmaf(x1, x1, fmaf(y1, y1, z1*z1)));
    }

    // ---- load this thread's OPT outer points ----
    float px[OPT], py[OPT], pz[OPT], rq[OPT];
    const int gbase = och * PTSBLK;
#pragma unroll
    for (int o = 0; o < OPT; o++) {
        int i = gbase + o * T + tid;
        px[o] = outer[3*i]; py[o] = outer[3*i+1]; pz[o] = outer[3*i+2];
        rq[o] = fmaf(px[o], px[o], fmaf(py[o], py[o], pz[o]*pz[o]));
    }

    // ---- block argmax radius (deterministic tie-break: lowest local idx) ----
    {
        float r = rq[0]; int li = tid;
#pragma unroll
        for (int o = 1; o < OPT; o++) {
            int l = o * T + tid;
            if (rq[o] > r || (rq[o] == r && l < li)) { r = rq[o]; li = l; }
        }
#pragma unroll
        for (int off = 16; off; off >>= 1) {
            float r2 = __shfl_xor_sync(0xffffffffu, r, off);
            int   l2 = __shfl_xor_sync(0xffffffffu, li, off);
            if (r2 > r || (r2 == r && l2 < li)) { r = r2; li = l2; }
        }
        if ((tid & 31) == 0) { s_red[tid >> 5] = r; s_redi[tid >> 5] = li; }
    }
    __syncthreads();        // staging + argmax partials visible
    if (tid == 0) {
        float r = s_red[0]; int li = s_redi[0];
#pragma unroll
        for (int w = 1; w < T / 32; w++)
            if (s_red[w] > r || (s_red[w] == r && s_redi[w] < li)) { r = s_red[w]; li = s_redi[w]; }
        int gi = gbase + li;
        float cx = outer[3*gi], cy = outer[3*gi+1], cz = outer[3*gi+2];
        s_cand[0] = cx; s_cand[1] = cy; s_cand[2] = cz;
        s_cand[3] = fmaf(cx, cx, fmaf(cy, cy, cz*cz));
    }
    __syncthreads();

    // ---- LB: exact full min of candidate over ALL inner points ----
    {
        const float cx = s_cand[0], cy = s_cand[1], cz = s_cand[2];
        float mn = FLT_MAX;
#pragma unroll
        for (int k = 0; k < NSLOTS / T; k++) {
            const float* e = shf + (tid + k * T) * 8;
            float t0 = fmaf(e[0], cx, e[6]);
            t0 = fmaf(e[2], cy, t0);
            t0 = fmaf(e[4], cz, t0);
            float t1 = fmaf(e[1], cx, e[7]);
            t1 = fmaf(e[3], cy, t1);
            t1 = fmaf(e[5], cz, t1);
            mn = fminf(mn, fminf(t0, t1));
        }
#pragma unroll
        for (int off = 16; off; off >>= 1)
            mn = fminf(mn, __shfl_xor_sync(0xffffffffu, mn, off));
        if ((tid & 31) == 0) s_red[tid >> 5] = mn;
    }
    __syncthreads();
    if (tid == 0) {
        float m = s_red[0];
#pragma unroll
        for (int w = 1; w < T / 32; w++) m = fminf(m, s_red[w]);
        float lb = m + s_cand[3];
        s_lb = lb - fabsf(lb) * 1e-5f - 1e-12f;
    }
    __syncthreads();

    // ---- Phase 1: branchless scan of first P1SLOTS slots, OPT=4 ----
    {
        u64t px2[OPT], py2[OPT], pz2[OPT];
        float mn[OPT];
#pragma unroll
        for (int o = 0; o < OPT; o++) {
            px2[o] = pk(px[o], px[o]);
            py2[o] = pk(py[o], py[o]);
            pz2[o] = pk(pz[o], pz[o]);
            mn[o]  = FLT_MAX;
        }
#pragma unroll 8
        for (int s = 0; s < P1SLOTS; s++) {
            ulonglong2 ab = shv[s * 2 + 0];
            ulonglong2 cd = shv[s * 2 + 1];
#pragma unroll
            for (int o = 0; o < OPT; o++) {
                u64t t = fma2(ab.x, px2[o], cd.y);
                t = fma2(ab.y, py2[o], t);
                t = fma2(cd.x, pz2[o], t);
                float2 tv = upk(t);
                mn[o] = fminf(mn[o], fminf(tv.x, tv.y));
            }
        }
        const float lbm = s_lb;
#pragma unroll
        for (int o = 0; o < OPT; o++) {
            int li = o * T + tid;
            float v = mn[o] + rq[o];
            s_val[li] = v;
            if (v >= lbm) {                              // not certified
                int k = atomicAdd(&s_cnt, 1);
                s_list[k] = (unsigned short)li;
            }
        }
    }
    __syncthreads();

    // ---- Phase 2: warp-per-point rescan of remaining slots with break ----
    {
        const int wid = tid >> 5, lane = tid & 31;
        const int cnt = s_cnt;
        const float lbm = s_lb;
        for (int u = wid; u < cnt; u += T / 32) {
            const int li = s_list[u];
            const int gi = gbase + li;
            const float x = outer[3*gi], y = outer[3*gi+1], z = outer[3*gi+2];
            const float prq = fmaf(x, x, fmaf(y, y, z*z));
            const u64t px2 = pk(x, x), py2 = pk(y, y), pz2 = pk(z, z);
            const float thr = lbm - prq;                 // s-domain threshold

            float m = FLT_MAX;
            for (int base = 0; base < P2ITER; base += 8) {
#pragma unroll
                for (int k = 0; k < 8; k++) {
                    int slot = P1SLOTS + (base + k) * 32 + lane;
                    ulonglong2 ab = shv[slot * 2 + 0];
                    ulonglong2 cd = shv[slot * 2 + 1];
                    u64t t = fma2(ab.x, px2, cd.y);
                    t = fma2(ab.y, py2, t);
                    t = fma2(cd.x, pz2, t);
                    float2 tv = upk(t);
                    m = fminf(m, fminf(tv.x, tv.y));
                }
                if (__any_sync(0xffffffffu, m < thr)) break;   // certified
            }
#pragma unroll
            for (int off = 16; off; off >>= 1)
                m = fminf(m, __shfl_xor_sync(0xffffffffu, m, off));
            if (lane == 0)
                s_val[li] = fminf(s_val[li], m + prq);
        }
    }
    __syncthreads();

    // ---- block max over s_val ----
    {
        float v = s_val[tid];
#pragma unroll
        for (int o = 1; o < OPT; o++) v = fmaxf(v, s_val[o * T + tid]);
#pragma unroll
        for (int off = 16; off; off >>= 1)
            v = fmaxf(v, __shfl_xor_sync(0xffffffffu, v, off));
        if ((tid & 31) == 0) s_red[tid >> 5] = v;
    }
    __syncthreads();
    if (tid == 0) {
        float m = s_red[0];
#pragma unroll
        for (int w = 1; w < T / 32; w++) m = fmaxf(m, s_red[w]);
        g_bmax[dir][b][och] = m;
    }
}

__global__ void hd_combine(float* __restrict__ out) {
    const int b = blockIdx.x, tid = threadIdx.x;        // 32 threads
    float v0 = (tid < OCH) ? g_bmax[0][b][tid] : -FLT_MAX;
    float v1 = (tid < OCH) ? g_bmax[1][b][tid] : -FLT_MAX;
#pragma unroll
    for (int off = 16; off; off >>= 1) {
        v0 = fmaxf(v0, __shfl_xor_sync(0xffffffffu, v0, off));
        v1 = fmaxf(v1, __shfl_xor_sync(0xffffffffu, v1, off));
    }
    if (tid == 0) out[b] = 0.5f * (v0 + v1);
}

extern "C" void kernel_launch(void* const* d_in, const int* in_sizes, int n_in,
                              void* d_out, int out_size) {
    const float* preds = (const float*)d_in[0];
    const float* gts   = (const float*)d_in[1];
    float* out = (float*)d_out;

    const int smem = NSLOTS * 2 * sizeof(ulonglong2);   // 64 KB dynamic
    cudaFuncSetAttribute(hd_main,
                         cudaFuncAttributeMaxDynamicSharedMemorySize, smem);

    hd_main<<<dim3(OCH, BATCH, 2), T, smem>>>(preds, gts);   // 4x16x2 = 128
    hd_combine<<<BATCH, 32>>>(out);
}